// round 4
// baseline (speedup 1.0000x reference)
#include <cuda_runtime.h>
#include <float.h>
#include <stdint.h>

#define NB 32
#define NC 80
#define HH 128
#define WW 128
#define HWSZ 16384
#define KTOP 100
#define SCORE_THRESH 0.3f
#define NMS_THRESH 0.3f

// scratch (device globals: allocation-free)
__device__ float g_conf[NB * HWSZ];          // thresholded scores
__device__ unsigned char g_cls[NB * HWSZ];   // argmax channel

__device__ __forceinline__ float4 neg4() {
    return make_float4(-FLT_MAX, -FLT_MAX, -FLT_MAX, -FLT_MAX);
}

// ---------------------------------------------------------------------------
// Kernel A: 3x3 peak-NMS + channel max/argmax.
// Warp owns 2 output rows x 128 cols (4 cols per lane, float4).
// Horizontal 3-max via shuffles, vertical 3-max over 4 loaded rows.
// ---------------------------------------------------------------------------
__global__ void __launch_bounds__(256, 2) peak_kernel(const float* __restrict__ hm) {
    const int b    = blockIdx.y;
    const int warp = threadIdx.x >> 5;
    const int lane = threadIdx.x & 31;
    const int y0   = (blockIdx.x << 4) + (warp << 1);   // output rows y0, y0+1
    const int x0   = lane << 2;

    const float* __restrict__ base = hm + (size_t)b * NC * HWSZ + x0;
    const bool topOK = (y0 > 0);
    const bool botOK = (y0 + 2 < HH);

    float4 best0 = make_float4(0.f, 0.f, 0.f, 0.f);
    float4 best1 = make_float4(0.f, 0.f, 0.f, 0.f);
    int bc0x = 0, bc0y = 0, bc0z = 0, bc0w = 0;
    int bc1x = 0, bc1y = 0, bc1z = 0, bc1w = 0;

    for (int c = 0; c < NC; ++c) {
        const float* p = base + (size_t)c * HWSZ;
        float4 v0 = topOK ? *(const float4*)(p + (y0 - 1) * WW) : neg4();
        float4 v1 = *(const float4*)(p + (y0 + 0) * WW);
        float4 v2 = *(const float4*)(p + (y0 + 1) * WW);
        float4 v3 = botOK ? *(const float4*)(p + (y0 + 2) * WW) : neg4();

        float l0 = __shfl_up_sync(0xffffffffu, v0.w, 1);
        float l1 = __shfl_up_sync(0xffffffffu, v1.w, 1);
        float l2 = __shfl_up_sync(0xffffffffu, v2.w, 1);
        float l3 = __shfl_up_sync(0xffffffffu, v3.w, 1);
        float r0 = __shfl_down_sync(0xffffffffu, v0.x, 1);
        float r1 = __shfl_down_sync(0xffffffffu, v1.x, 1);
        float r2 = __shfl_down_sync(0xffffffffu, v2.x, 1);
        float r3 = __shfl_down_sync(0xffffffffu, v3.x, 1);
        if (lane == 0)  { l0 = l1 = l2 = l3 = -FLT_MAX; }
        if (lane == 31) { r0 = r1 = r2 = r3 = -FLT_MAX; }

#define HMAXROW(h, v, l, r)                          \
        h.x = fmaxf(fmaxf(l,   v.x), v.y);           \
        h.y = fmaxf(fmaxf(v.x, v.y), v.z);           \
        h.z = fmaxf(fmaxf(v.y, v.z), v.w);           \
        h.w = fmaxf(fmaxf(v.z, v.w), r);

        float4 h0, h1, h2, h3;
        HMAXROW(h0, v0, l0, r0)
        HMAXROW(h1, v1, l1, r1)
        HMAXROW(h2, v2, l2, r2)
        HMAXROW(h3, v3, l3, r3)
#undef HMAXROW

#define V3(a, b_, c_) fmaxf(fmaxf((a), (b_)), (c_))
#define UPD(val, vm, bst, bcv)                                 \
        { float m_ = ((val) == (vm)) ? (val) : 0.0f;           \
          if (m_ > (bst)) { (bst) = m_; (bcv) = c; } }

        // output row y0 : center v1, window h0,h1,h2
        UPD(v1.x, V3(h0.x, h1.x, h2.x), best0.x, bc0x)
        UPD(v1.y, V3(h0.y, h1.y, h2.y), best0.y, bc0y)
        UPD(v1.z, V3(h0.z, h1.z, h2.z), best0.z, bc0z)
        UPD(v1.w, V3(h0.w, h1.w, h2.w), best0.w, bc0w)
        // output row y0+1 : center v2, window h1,h2,h3
        UPD(v2.x, V3(h1.x, h2.x, h3.x), best1.x, bc1x)
        UPD(v2.y, V3(h1.y, h2.y, h3.y), best1.y, bc1y)
        UPD(v2.z, V3(h1.z, h2.z, h3.z), best1.z, bc1z)
        UPD(v2.w, V3(h1.w, h2.w, h3.w), best1.w, bc1w)
#undef UPD
#undef V3
    }

    const int o0 = (b << 14) + (y0 + 0) * WW + x0;
    const int o1 = (b << 14) + (y0 + 1) * WW + x0;
    float4 s0, s1;
    s0.x = best0.x > SCORE_THRESH ? best0.x : 0.f;
    s0.y = best0.y > SCORE_THRESH ? best0.y : 0.f;
    s0.z = best0.z > SCORE_THRESH ? best0.z : 0.f;
    s0.w = best0.w > SCORE_THRESH ? best0.w : 0.f;
    s1.x = best1.x > SCORE_THRESH ? best1.x : 0.f;
    s1.y = best1.y > SCORE_THRESH ? best1.y : 0.f;
    s1.z = best1.z > SCORE_THRESH ? best1.z : 0.f;
    s1.w = best1.w > SCORE_THRESH ? best1.w : 0.f;
    *(float4*)(g_conf + o0) = s0;
    *(float4*)(g_conf + o1) = s1;
    *(uchar4*)(g_cls + o0) = make_uchar4((unsigned char)bc0x, (unsigned char)bc0y,
                                         (unsigned char)bc0z, (unsigned char)bc0w);
    *(uchar4*)(g_cls + o1) = make_uchar4((unsigned char)bc1x, (unsigned char)bc1y,
                                         (unsigned char)bc1z, (unsigned char)bc1w);
}

// ---------------------------------------------------------------------------
// Kernel B: per-batch exact top-100 (bisection on float bits over
// register-resident keys), bitonic sort, gather, greedy per-class NMS, decode.
// ---------------------------------------------------------------------------
__global__ void __launch_bounds__(512) select_kernel(const float* __restrict__ wh,
                                                     const float* __restrict__ off,
                                                     float* __restrict__ out) {
    const int b = blockIdx.x;
    const int tid = threadIdx.x;

    __shared__ int s_cnt;
    __shared__ int s_n;
    __shared__ unsigned long long cand[256];
    __shared__ float s_x1[KTOP], s_y1[KTOP], s_x2[KTOP], s_y2[KTOP];
    __shared__ float s_area[KTOP], s_score[KTOP];
    __shared__ int s_cls[KTOP];
    __shared__ int s_keep[KTOP];

    // load 32 score keys per thread into registers (coalesced)
    const float* cf = g_conf + (size_t)b * HWSZ;
    unsigned int key[32];
#pragma unroll
    for (int i = 0; i < 32; ++i)
        key[i] = __float_as_uint(cf[i * 512 + tid]);   // idx = i*512 + tid

    // ---- exact 100th-largest key via bisection on the (nonneg) float bits ----
    unsigned int lo = 0u, hi = 0x40000000u;   // all keys < 1.0f < 2.0f
    if (tid == 0) s_cnt = 0;
    __syncthreads();
    while (hi - lo > 1u) {
        unsigned int mid = (lo + hi) >> 1;
        int c = 0;
#pragma unroll
        for (int i = 0; i < 32; ++i) c += (key[i] >= mid);
        c = __reduce_add_sync(0xffffffffu, c);
        if ((tid & 31) == 0) atomicAdd(&s_cnt, c);
        __syncthreads();
        int cnt = s_cnt;
        __syncthreads();
        if (tid == 0) s_cnt = 0;
        if (cnt >= KTOP) lo = mid; else hi = mid;
        __syncthreads();
    }
    // lo = value at rank 100 (0 if fewer than 100 positive scores)
    unsigned int thrK = (lo > 0u) ? lo : 1u;

    // ---- compact candidates key >= thrK, packed (key<<32)|~idx ----
    if (tid == 0) s_n = 0;
    __syncthreads();
#pragma unroll
    for (int i = 0; i < 32; ++i) {
        if (key[i] >= thrK) {
            int p = atomicAdd(&s_n, 1);
            if (p < 256) {
                unsigned int idx = (unsigned int)(i * 512 + tid);
                cand[p] = ((unsigned long long)key[i] << 32) | (unsigned int)(~idx);
            }
        }
    }
    __syncthreads();
    int n = s_n < 256 ? s_n : 256;
    for (int p = n + tid; p < 256; p += 512) cand[p] = 0ULL;
    __syncthreads();

    // ---- bitonic sort 256 descending ----
    for (int ksz = 2; ksz <= 256; ksz <<= 1) {
        for (int j = ksz >> 1; j > 0; j >>= 1) {
            if (tid < 256) {
                int i = tid;
                int l = i ^ j;
                if (l > i) {
                    unsigned long long a = cand[i], bb = cand[l];
                    bool up = ((i & ksz) == 0);
                    if (up ? (a < bb) : (a > bb)) { cand[i] = bb; cand[l] = a; }
                }
            }
            __syncthreads();
        }
    }

    // ---- gather top-100, decode boxes (mirrors reference FP op order) ----
    if (tid < KTOP) {
        unsigned long long pk = cand[tid];
        unsigned int kk = (unsigned int)(pk >> 32);
        float score = __uint_as_float(kk);
        bool valid = score > SCORE_THRESH;
        float x1 = 0.f, y1 = 0.f, x2 = 0.f, y2 = 0.f;
        int cl = 0;
        if (valid) {
            unsigned int idx = ~((unsigned int)(pk & 0xffffffffu));
            int xi = idx & (WW - 1);
            int yi = idx >> 7;
            const float* whb = wh  + (size_t)b * 2 * HWSZ;
            const float* ofb = off + (size_t)b * 2 * HWSZ;
            float bw = whb[idx];
            float bh = whb[HWSZ + idx];
            float o0 = ofb[idx];
            float o1 = ofb[HWSZ + idx];
            float cx = (float)xi + o0;
            float cy = (float)yi + o1;
            const float invW = 1.0f / (float)WW;   // exact power of two
            const float invH = 1.0f / (float)HH;
            x1 = (cx - bw * 0.5f) * invW;
            y1 = (cy - bh * 0.5f) * invH;
            x2 = (cx + bw * 0.5f) * invW;
            y2 = (cy + bh * 0.5f) * invH;
            cl = (int)g_cls[(size_t)b * HWSZ + idx];
        }
        s_x1[tid] = x1; s_y1[tid] = y1; s_x2[tid] = x2; s_y2[tid] = y2;
        s_area[tid] = (x2 - x1) * (y2 - y1);
        s_score[tid] = score;
        s_cls[tid] = cl;
        s_keep[tid] = valid ? 1 : 0;
    }
    __syncthreads();

    // ---- greedy per-class NMS (sequential over i, parallel over j) ----
    for (int i = 0; i < KTOP - 1; ++i) {
        if (tid < KTOP && tid > i) {
            if (s_keep[i] && s_cls[tid] == s_cls[i]) {
                float lx = fmaxf(s_x1[i], s_x1[tid]);
                float ly = fmaxf(s_y1[i], s_y1[tid]);
                float rx = fminf(s_x2[i], s_x2[tid]);
                float ry = fminf(s_y2[i], s_y2[tid]);
                float iw = fmaxf(rx - lx, 0.f);
                float ih = fmaxf(ry - ly, 0.f);
                float inter = iw * ih;
                float iou = inter / (s_area[i] + s_area[tid] - inter + 1e-9f);
                if (iou > NMS_THRESH) s_keep[tid] = 0;
            }
        }
        __syncthreads();
    }

    // ---- write dets (scale to image via the reference's recompute path) ----
    if (tid < KTOP) {
        float* o = out + ((size_t)b * KTOP + tid) * 6;
        if (s_keep[tid]) {
            float x1 = s_x1[tid], y1 = s_y1[tid], x2 = s_x2[tid], y2 = s_y2[tid];
            float cxm = (x1 + x2) * 0.5f;          // (tb01+tb23)/2
            float cym = (y1 + y2) * 0.5f;
            float cw = x2 - x1;
            float ch = y2 - y1;
            float mnx = cxm - cw * 0.5f;           // cxy - cwh/2
            float mny = cym - ch * 0.5f;
            float mxx = cxm + cw * 0.5f;
            float mxy = cym + ch * 0.5f;
            o[0] = mnx * 512.f;
            o[1] = mny * 512.f;
            o[2] = mxx * 512.f;
            o[3] = mxy * 512.f;
            o[4] = s_score[tid];
            o[5] = (float)s_cls[tid];
        } else {
            o[0] = 0.f; o[1] = 0.f; o[2] = 0.f;
            o[3] = 0.f; o[4] = 0.f; o[5] = 0.f;
        }
    }
}

extern "C" void kernel_launch(void* const* d_in, const int* in_sizes, int n_in,
                              void* d_out, int out_size) {
    const float* hm  = (const float*)d_in[0];
    const float* wh  = (const float*)d_in[1];
    const float* off = (const float*)d_in[2];
    float* out = (float*)d_out;

    dim3 gA(HH / 16, NB);     // 8 x 32 = 256 blocks
    peak_kernel<<<gA, 256>>>(hm);
    select_kernel<<<NB, 512>>>(wh, off, out);
}

// round 5
// speedup vs baseline: 1.2411x; 1.2411x over previous
#include <cuda_runtime.h>
#include <float.h>
#include <stdint.h>

#define NB 32
#define NC 80
#define HH 128
#define WW 128
#define HWSZ 16384
#define KTOP 100
#define SCORE_THRESH 0.3f
#define NMS_THRESH 0.3f
#define MAXCAND 256

// scratch (device globals: allocation-free)
__device__ float g_conf[NB * HWSZ];          // thresholded scores
__device__ unsigned char g_cls[NB * HWSZ];   // argmax channel

__device__ __forceinline__ float4 neg4() {
    return make_float4(-FLT_MAX, -FLT_MAX, -FLT_MAX, -FLT_MAX);
}

// ---------------------------------------------------------------------------
// Kernel A: 3x3 peak-NMS + channel max/argmax.
// Warp owns 2 output rows x 128 cols (4 cols/lane, float4).
// Software-pipelined over channels (prefetch next channel's rows) so the
// DRAM latency is hidden behind the max/argmax compute of the current one.
// Separable 3x3 max: shared vertical pair-max, then horizontal 3-max.
// ---------------------------------------------------------------------------
__global__ void __launch_bounds__(256, 2) peak_kernel(const float* __restrict__ hm) {
    const int b    = blockIdx.y;
    const int warp = threadIdx.x >> 5;
    const int lane = threadIdx.x & 31;
    const int y0   = (blockIdx.x << 4) + (warp << 1);   // output rows y0, y0+1
    const int x0   = lane << 2;

    const float* __restrict__ base = hm + (size_t)b * NC * HWSZ + x0;
    const bool topOK = (y0 > 0);
    const bool botOK = (y0 + 2 < HH);

    float best[8] = {0.f, 0.f, 0.f, 0.f, 0.f, 0.f, 0.f, 0.f};
    int   bc[8]   = {0, 0, 0, 0, 0, 0, 0, 0};

    float4 v0, v1, v2, v3, n0, n1, n2, n3;
    {
        const float* p = base;
        v0 = topOK ? *(const float4*)(p + (y0 - 1) * WW) : neg4();
        v1 = *(const float4*)(p + (y0 + 0) * WW);
        v2 = *(const float4*)(p + (y0 + 1) * WW);
        v3 = botOK ? *(const float4*)(p + (y0 + 2) * WW) : neg4();
    }

    for (int c = 0; c < NC; ++c) {
        if (c + 1 < NC) {
            const float* q = base + (size_t)(c + 1) * HWSZ;
            n0 = topOK ? *(const float4*)(q + (y0 - 1) * WW) : neg4();
            n1 = *(const float4*)(q + (y0 + 0) * WW);
            n2 = *(const float4*)(q + (y0 + 1) * WW);
            n3 = botOK ? *(const float4*)(q + (y0 + 2) * WW) : neg4();
        }

        // separable vertical max (share max(v1,v2))
        float4 t, cma, cmb;
        t.x = fmaxf(v1.x, v2.x); t.y = fmaxf(v1.y, v2.y);
        t.z = fmaxf(v1.z, v2.z); t.w = fmaxf(v1.w, v2.w);
        cma.x = fmaxf(t.x, v0.x); cma.y = fmaxf(t.y, v0.y);
        cma.z = fmaxf(t.z, v0.z); cma.w = fmaxf(t.w, v0.w);
        cmb.x = fmaxf(t.x, v3.x); cmb.y = fmaxf(t.y, v3.y);
        cmb.z = fmaxf(t.z, v3.z); cmb.w = fmaxf(t.w, v3.w);

        float la = __shfl_up_sync(0xffffffffu, cma.w, 1);
        float ra = __shfl_down_sync(0xffffffffu, cma.x, 1);
        float lb = __shfl_up_sync(0xffffffffu, cmb.w, 1);
        float rb = __shfl_down_sync(0xffffffffu, cmb.x, 1);
        if (lane == 0)  { la = -FLT_MAX; lb = -FLT_MAX; }
        if (lane == 31) { ra = -FLT_MAX; rb = -FLT_MAX; }

        // horizontal 3-max via shared pair maxes
        float pa01 = fmaxf(cma.x, cma.y), pa12 = fmaxf(cma.y, cma.z), pa23 = fmaxf(cma.z, cma.w);
        float pb01 = fmaxf(cmb.x, cmb.y), pb12 = fmaxf(cmb.y, cmb.z), pb23 = fmaxf(cmb.z, cmb.w);
        float ha0 = fmaxf(la, pa01),   ha1 = fmaxf(pa01, cma.z);
        float ha2 = fmaxf(pa12, cma.w), ha3 = fmaxf(pa23, ra);
        float hb0 = fmaxf(lb, pb01),   hb1 = fmaxf(pb01, cmb.z);
        float hb2 = fmaxf(pb12, cmb.w), hb3 = fmaxf(pb23, rb);

#define UPD(val, h, k)                                             \
        { if ((val) == (h) && (val) > best[k]) { best[k] = (val); bc[k] = c; } }
        UPD(v1.x, ha0, 0) UPD(v1.y, ha1, 1) UPD(v1.z, ha2, 2) UPD(v1.w, ha3, 3)
        UPD(v2.x, hb0, 4) UPD(v2.y, hb1, 5) UPD(v2.z, hb2, 6) UPD(v2.w, hb3, 7)
#undef UPD

        if (c + 1 < NC) { v0 = n0; v1 = n1; v2 = n2; v3 = n3; }
    }

    const int o0 = (b << 14) + (y0 + 0) * WW + x0;
    const int o1 = (b << 14) + (y0 + 1) * WW + x0;
    float4 s0, s1;
    s0.x = best[0] > SCORE_THRESH ? best[0] : 0.f;
    s0.y = best[1] > SCORE_THRESH ? best[1] : 0.f;
    s0.z = best[2] > SCORE_THRESH ? best[2] : 0.f;
    s0.w = best[3] > SCORE_THRESH ? best[3] : 0.f;
    s1.x = best[4] > SCORE_THRESH ? best[4] : 0.f;
    s1.y = best[5] > SCORE_THRESH ? best[5] : 0.f;
    s1.z = best[6] > SCORE_THRESH ? best[6] : 0.f;
    s1.w = best[7] > SCORE_THRESH ? best[7] : 0.f;
    *(float4*)(g_conf + o0) = s0;
    *(float4*)(g_conf + o1) = s1;
    *(uchar4*)(g_cls + o0) = make_uchar4((unsigned char)bc[0], (unsigned char)bc[1],
                                         (unsigned char)bc[2], (unsigned char)bc[3]);
    *(uchar4*)(g_cls + o1) = make_uchar4((unsigned char)bc[4], (unsigned char)bc[5],
                                         (unsigned char)bc[6], (unsigned char)bc[7]);
}

// ---------------------------------------------------------------------------
// Kernel B: per-batch top-100 via histogram threshold, warp-register bitonic
// sort, gather, bitmask greedy per-class NMS, decode. Minimal barrier rounds.
// ---------------------------------------------------------------------------
__global__ void __launch_bounds__(512) select_kernel(const float* __restrict__ wh,
                                                     const float* __restrict__ off,
                                                     float* __restrict__ out) {
    const int b = blockIdx.x;
    const int tid = threadIdx.x;

    __shared__ int s_hist[4096];
    __shared__ int s_scanA[512], s_scanB[512];
    __shared__ unsigned long long s_cand[MAXCAND];
    __shared__ float s_x1[KTOP], s_y1[KTOP], s_x2[KTOP], s_y2[KTOP];
    __shared__ float s_area[KTOP], s_score[KTOP];
    __shared__ int s_cls[KTOP];
    __shared__ uint4 s_sup[KTOP];
    __shared__ unsigned int s_alive[4];
    __shared__ int s_binCnt[2];     // [cutoff bin, count >= threshold]
    __shared__ int s_n;

    // ---- load 32 score keys per thread into registers (coalesced) ----
    const float* cf = g_conf + (size_t)b * HWSZ;
    unsigned int key[32];
#pragma unroll
    for (int i = 0; i < 32; ++i)
        key[i] = __float_as_uint(cf[i * 512 + tid]);   // idx = i*512 + tid

    // ---- histogram-based rank-100 threshold (nonzero keys are in (0.3, 1)) ----
    unsigned int hbase = 0x3E800000u;   // 0.25f bits
    int shift = 12;
    int above = 0;
    unsigned int thr = hbase;
    int cnt = 0;

    for (int pass = 0; pass < 2; ++pass) {
#pragma unroll
        for (int i = 0; i < 8; ++i) s_hist[i * 512 + tid] = 0;
        if (tid == 0) { s_binCnt[0] = -1; s_binCnt[1] = 0; }
        __syncthreads();
#pragma unroll
        for (int i = 0; i < 32; ++i) {
            if (key[i] >= hbase) {
                unsigned int bin = (key[i] - hbase) >> shift;
                if (bin < 4096u) atomicAdd(&s_hist[bin], 1);
            }
        }
        __syncthreads();
        int part = 0;
#pragma unroll
        for (int k = 0; k < 8; ++k) part += s_hist[tid * 8 + k];
        s_scanA[tid] = part;
        __syncthreads();
        // suffix scan (Hillis-Steele, ping-pong)
        int* src = s_scanA;
        int* dst = s_scanB;
        for (int o = 1; o < 512; o <<= 1) {
            int v = src[tid] + ((tid + o < 512) ? src[tid + o] : 0);
            dst[tid] = v;
            __syncthreads();
            int* tmp = src; src = dst; dst = tmp;
        }
        int S = src[tid];
        int Snext = (tid < 511) ? src[tid + 1] : 0;
        if (above + S >= KTOP && above + Snext < KTOP) {
            int run = above + Snext;
            for (int k = 7; k >= 0; --k) {
                run += s_hist[tid * 8 + k];
                if (run >= KTOP) { s_binCnt[0] = tid * 8 + k; s_binCnt[1] = run; break; }
            }
        }
        __syncthreads();
        int bin = s_binCnt[0];
        int total = above + src[0];
        if (bin < 0) {               // fewer than KTOP positive scores: take all
            thr = hbase;
            cnt = total;
            break;
        }
        cnt = s_binCnt[1];
        int hbin = s_hist[bin];
        thr = hbase + ((unsigned int)bin << shift);
        if (cnt <= MAXCAND || shift == 0) break;
        // refine inside cutoff bin at 1-ulp granularity
        above = cnt - hbin;
        hbase = thr;
        shift = 0;
        __syncthreads();
    }

    // ---- compact candidates key >= thr, packed (key<<32)|~idx ----
    if (tid == 0) s_n = 0;
    __syncthreads();
#pragma unroll
    for (int i = 0; i < 32; ++i) {
        if (key[i] >= thr && key[i] != 0u) {
            int p = atomicAdd(&s_n, 1);
            if (p < MAXCAND) {
                unsigned int idx = (unsigned int)(i * 512 + tid);
                s_cand[p] = ((unsigned long long)key[i] << 32) | (unsigned int)(~idx);
            }
        }
    }
    __syncthreads();
    int n = s_n < MAXCAND ? s_n : MAXCAND;
    for (int p = n + tid; p < MAXCAND; p += 512) s_cand[p] = 0ULL;
    __syncthreads();

    // ---- warp-0 register bitonic sort of 256 u64, descending ----
    if (tid < 32) {
        unsigned long long v[8];
#pragma unroll
        for (int r = 0; r < 8; ++r) v[r] = s_cand[r * 32 + tid];
#pragma unroll
        for (int k = 2; k <= 256; k <<= 1) {
#pragma unroll
            for (int j = 128; j > 0; j >>= 1) {
                if (j >= k) continue;
                if (j >= 32) {
                    int jr = j >> 5;
#pragma unroll
                    for (int r = 0; r < 8; ++r) {
                        if ((r & jr) == 0) {
                            int pr = r | jr;
                            int idx = r * 32 + tid;
                            bool desc = ((idx & k) == 0);
                            unsigned long long a = v[r], bb = v[pr];
                            bool sw = desc ? (a < bb) : (a > bb);
                            if (sw) { v[r] = bb; v[pr] = a; }
                        }
                    }
                } else {
#pragma unroll
                    for (int r = 0; r < 8; ++r) {
                        unsigned long long pv = __shfl_xor_sync(0xffffffffu, v[r], j);
                        int idx = r * 32 + tid;
                        bool desc = ((idx & k) == 0);
                        bool low = ((tid & j) == 0);
                        bool keepMax = (desc == low);
                        unsigned long long mx = v[r] > pv ? v[r] : pv;
                        unsigned long long mn = v[r] > pv ? pv : v[r];
                        v[r] = keepMax ? mx : mn;
                    }
                }
            }
        }
#pragma unroll
        for (int r = 0; r < 8; ++r) s_cand[r * 32 + tid] = v[r];
    }
    if (tid < 4) s_alive[tid] = 0u;
    if (tid < KTOP) s_sup[tid] = make_uint4(0u, 0u, 0u, 0u);
    __syncthreads();

    // ---- gather top-100, decode boxes (mirrors reference FP op order) ----
    if (tid < KTOP) {
        unsigned long long pk = s_cand[tid];
        unsigned int kk = (unsigned int)(pk >> 32);
        float score = __uint_as_float(kk);
        bool valid = score > SCORE_THRESH;
        float x1 = 0.f, y1 = 0.f, x2 = 0.f, y2 = 0.f;
        int cl = 0;
        if (valid) {
            unsigned int idx = ~((unsigned int)(pk & 0xffffffffu));
            int xi = idx & (WW - 1);
            int yi = idx >> 7;
            const float* whb = wh  + (size_t)b * 2 * HWSZ;
            const float* ofb = off + (size_t)b * 2 * HWSZ;
            float bw = whb[idx];
            float bh = whb[HWSZ + idx];
            float o0 = ofb[idx];
            float o1 = ofb[HWSZ + idx];
            float cx = (float)xi + o0;
            float cy = (float)yi + o1;
            const float invW = 1.0f / (float)WW;   // exact power of two
            const float invH = 1.0f / (float)HH;
            x1 = (cx - bw * 0.5f) * invW;
            y1 = (cy - bh * 0.5f) * invH;
            x2 = (cx + bw * 0.5f) * invW;
            y2 = (cy + bh * 0.5f) * invH;
            cl = (int)g_cls[(size_t)b * HWSZ + idx];
            atomicOr(&s_alive[tid >> 5], 1u << (tid & 31));
        }
        s_x1[tid] = x1; s_y1[tid] = y1; s_x2[tid] = x2; s_y2[tid] = y2;
        s_area[tid] = (x2 - x1) * (y2 - y1);
        s_score[tid] = score;
        s_cls[tid] = cl;
    }
    __syncthreads();

    // ---- parallel suppression-matrix build (bitmask rows) ----
    for (int idx = tid; idx < KTOP * KTOP; idx += 512) {
        int i = idx / KTOP;
        int jj = idx - i * KTOP;
        if (jj > i && s_cls[i] == s_cls[jj]) {
            float lx = fmaxf(s_x1[i], s_x1[jj]);
            float ly = fmaxf(s_y1[i], s_y1[jj]);
            float rx = fminf(s_x2[i], s_x2[jj]);
            float ry = fminf(s_y2[i], s_y2[jj]);
            float iw = fmaxf(rx - lx, 0.f);
            float ih = fmaxf(ry - ly, 0.f);
            float inter = iw * ih;
            float iou = inter / (s_area[i] + s_area[jj] - inter + 1e-9f);
            if (iou > NMS_THRESH)
                atomicOr(&((unsigned int*)s_sup)[i * 4 + (jj >> 5)], 1u << (jj & 31));
        }
    }
    __syncthreads();

    // ---- serial greedy sweep over bitmasks (thread 0, row prefetch) ----
    if (tid == 0) {
        unsigned int a0 = s_alive[0], a1 = s_alive[1], a2 = s_alive[2], a3 = s_alive[3];
        uint4 row = s_sup[0];
        for (int i = 0; i < KTOP; ++i) {
            uint4 nxt = (i + 1 < KTOP) ? s_sup[i + 1] : make_uint4(0u, 0u, 0u, 0u);
            unsigned int aw = (i < 32) ? a0 : (i < 64) ? a1 : (i < 96) ? a2 : a3;
            if ((aw >> (i & 31)) & 1u) {
                a0 &= ~row.x; a1 &= ~row.y; a2 &= ~row.z; a3 &= ~row.w;
            }
            row = nxt;
        }
        s_alive[0] = a0; s_alive[1] = a1; s_alive[2] = a2; s_alive[3] = a3;
    }
    __syncthreads();

    // ---- write dets (scale to image via the reference's recompute path) ----
    if (tid < KTOP) {
        bool alive = (s_alive[tid >> 5] >> (tid & 31)) & 1u;
        float* o = out + ((size_t)b * KTOP + tid) * 6;
        if (alive) {
            float x1 = s_x1[tid], y1 = s_y1[tid], x2 = s_x2[tid], y2 = s_y2[tid];
            float cxm = (x1 + x2) * 0.5f;
            float cym = (y1 + y2) * 0.5f;
            float cw = x2 - x1;
            float ch = y2 - y1;
            o[0] = (cxm - cw * 0.5f) * 512.f;
            o[1] = (cym - ch * 0.5f) * 512.f;
            o[2] = (cxm + cw * 0.5f) * 512.f;
            o[3] = (cym + ch * 0.5f) * 512.f;
            o[4] = s_score[tid];
            o[5] = (float)s_cls[tid];
        } else {
            o[0] = 0.f; o[1] = 0.f; o[2] = 0.f;
            o[3] = 0.f; o[4] = 0.f; o[5] = 0.f;
        }
    }
}

extern "C" void kernel_launch(void* const* d_in, const int* in_sizes, int n_in,
                              void* d_out, int out_size) {
    const float* hm  = (const float*)d_in[0];
    const float* wh  = (const float*)d_in[1];
    const float* off = (const float*)d_in[2];
    float* out = (float*)d_out;

    dim3 gA(HH / 16, NB);     // 8 x 32 = 256 blocks
    peak_kernel<<<gA, 256>>>(hm);
    select_kernel<<<NB, 512>>>(wh, off, out);
}

// round 10
// speedup vs baseline: 1.8183x; 1.4651x over previous
#include <cuda_runtime.h>
#include <float.h>
#include <stdint.h>

#define NB 32
#define NC 80
#define HH 128
#define WW 128
#define HWSZ 16384
#define KTOP 100
#define SCORE_THRESH 0.3f
#define NMS_THRESH 0.3f
#define MAXCAND 256

// scratch (device globals: allocation-free)
__device__ float g_conf[NB * HWSZ];          // thresholded scores
__device__ unsigned char g_cls[NB * HWSZ];   // argmax channel

__device__ __forceinline__ float4 neg4() {
    return make_float4(-FLT_MAX, -FLT_MAX, -FLT_MAX, -FLT_MAX);
}

// ---------------------------------------------------------------------------
// Kernel A: 3x3 peak-NMS + channel max/argmax.
// Warp owns 2 output rows x 128 cols (4 cols/lane, float4).
// 2-deep software pipeline over channels with 3 rotating register buffer
// sets: loads for channel c+2 are issued while channel c is consumed, so a
// warp's iteration no longer waits a full DRAM latency per channel.
// ---------------------------------------------------------------------------
__global__ void __launch_bounds__(256, 2) peak_kernel(const float* __restrict__ hm) {
    const int b    = blockIdx.y;
    const int warp = threadIdx.x >> 5;
    const int lane = threadIdx.x & 31;
    const int y0   = (blockIdx.x << 4) + (warp << 1);   // output rows y0, y0+1
    const int x0   = lane << 2;

    const float* __restrict__ base = hm + (size_t)b * NC * HWSZ + x0;
    const bool topOK = (y0 > 0);
    const bool botOK = (y0 + 2 < HH);

    float best[8] = {0.f, 0.f, 0.f, 0.f, 0.f, 0.f, 0.f, 0.f};
    int   bc[8]   = {0, 0, 0, 0, 0, 0, 0, 0};

    float4 A0, A1, A2, A3, B0, B1, B2, B3, C0, C1, C2, C3;

#define LOADCH(R0, R1, R2, R3, cch)                                      \
    { const float* p_ = base + (size_t)(cch) * HWSZ;                     \
      R0 = topOK ? *(const float4*)(p_ + (y0 - 1) * WW) : neg4();        \
      R1 = *(const float4*)(p_ + (y0 + 0) * WW);                         \
      R2 = *(const float4*)(p_ + (y0 + 1) * WW);                         \
      R3 = botOK ? *(const float4*)(p_ + (y0 + 2) * WW) : neg4(); }

#define COMPUTE(R0, R1, R2, R3, cch)                                                  \
    { float4 t_, cma_, cmb_;                                                          \
      t_.x = fmaxf(R1.x, R2.x); t_.y = fmaxf(R1.y, R2.y);                             \
      t_.z = fmaxf(R1.z, R2.z); t_.w = fmaxf(R1.w, R2.w);                             \
      cma_.x = fmaxf(t_.x, R0.x); cma_.y = fmaxf(t_.y, R0.y);                         \
      cma_.z = fmaxf(t_.z, R0.z); cma_.w = fmaxf(t_.w, R0.w);                         \
      cmb_.x = fmaxf(t_.x, R3.x); cmb_.y = fmaxf(t_.y, R3.y);                         \
      cmb_.z = fmaxf(t_.z, R3.z); cmb_.w = fmaxf(t_.w, R3.w);                         \
      float la_ = __shfl_up_sync(0xffffffffu, cma_.w, 1);                             \
      float ra_ = __shfl_down_sync(0xffffffffu, cma_.x, 1);                           \
      float lb_ = __shfl_up_sync(0xffffffffu, cmb_.w, 1);                             \
      float rb_ = __shfl_down_sync(0xffffffffu, cmb_.x, 1);                           \
      if (lane == 0)  { la_ = -FLT_MAX; lb_ = -FLT_MAX; }                             \
      if (lane == 31) { ra_ = -FLT_MAX; rb_ = -FLT_MAX; }                             \
      float pa01 = fmaxf(cma_.x, cma_.y), pa12 = fmaxf(cma_.y, cma_.z),               \
            pa23 = fmaxf(cma_.z, cma_.w);                                             \
      float pb01 = fmaxf(cmb_.x, cmb_.y), pb12 = fmaxf(cmb_.y, cmb_.z),               \
            pb23 = fmaxf(cmb_.z, cmb_.w);                                             \
      float ha0 = fmaxf(la_, pa01),   ha1 = fmaxf(pa01, cma_.z);                      \
      float ha2 = fmaxf(pa12, cma_.w), ha3 = fmaxf(pa23, ra_);                        \
      float hb0 = fmaxf(lb_, pb01),   hb1 = fmaxf(pb01, cmb_.z);                      \
      float hb2 = fmaxf(pb12, cmb_.w), hb3 = fmaxf(pb23, rb_);                        \
      if (R1.x == ha0 && R1.x > best[0]) { best[0] = R1.x; bc[0] = (cch); }           \
      if (R1.y == ha1 && R1.y > best[1]) { best[1] = R1.y; bc[1] = (cch); }           \
      if (R1.z == ha2 && R1.z > best[2]) { best[2] = R1.z; bc[2] = (cch); }           \
      if (R1.w == ha3 && R1.w > best[3]) { best[3] = R1.w; bc[3] = (cch); }           \
      if (R2.x == hb0 && R2.x > best[4]) { best[4] = R2.x; bc[4] = (cch); }           \
      if (R2.y == hb1 && R2.y > best[5]) { best[5] = R2.y; bc[5] = (cch); }           \
      if (R2.z == hb2 && R2.z > best[6]) { best[6] = R2.z; bc[6] = (cch); }           \
      if (R2.w == hb3 && R2.w > best[7]) { best[7] = R2.w; bc[7] = (cch); } }

    LOADCH(A0, A1, A2, A3, 0)
    LOADCH(B0, B1, B2, B3, 1)
#pragma unroll 1
    for (int c = 0; c < NC - 2; c += 3) {     // 26 iterations: c = 0..75
        LOADCH(C0, C1, C2, C3, c + 2)  COMPUTE(A0, A1, A2, A3, c)
        LOADCH(A0, A1, A2, A3, c + 3)  COMPUTE(B0, B1, B2, B3, c + 1)
        LOADCH(B0, B1, B2, B3, c + 4)  COMPUTE(C0, C1, C2, C3, c + 2)
    }
    COMPUTE(A0, A1, A2, A3, NC - 2)
    COMPUTE(B0, B1, B2, B3, NC - 1)
#undef LOADCH
#undef COMPUTE

    const int o0 = (b << 14) + (y0 + 0) * WW + x0;
    const int o1 = (b << 14) + (y0 + 1) * WW + x0;
    float4 s0, s1;
    s0.x = best[0] > SCORE_THRESH ? best[0] : 0.f;
    s0.y = best[1] > SCORE_THRESH ? best[1] : 0.f;
    s0.z = best[2] > SCORE_THRESH ? best[2] : 0.f;
    s0.w = best[3] > SCORE_THRESH ? best[3] : 0.f;
    s1.x = best[4] > SCORE_THRESH ? best[4] : 0.f;
    s1.y = best[5] > SCORE_THRESH ? best[5] : 0.f;
    s1.z = best[6] > SCORE_THRESH ? best[6] : 0.f;
    s1.w = best[7] > SCORE_THRESH ? best[7] : 0.f;
    *(float4*)(g_conf + o0) = s0;
    *(float4*)(g_conf + o1) = s1;
    *(uchar4*)(g_cls + o0) = make_uchar4((unsigned char)bc[0], (unsigned char)bc[1],
                                         (unsigned char)bc[2], (unsigned char)bc[3]);
    *(uchar4*)(g_cls + o1) = make_uchar4((unsigned char)bc[4], (unsigned char)bc[5],
                                         (unsigned char)bc[6], (unsigned char)bc[7]);
}

// ---------------------------------------------------------------------------
// Kernel B: per-batch top-100 via atomic-free ballot-count bisection on float
// bits, warp-register bitonic sort, gather, bitmask greedy per-class NMS.
// ---------------------------------------------------------------------------
__global__ void __launch_bounds__(512) select_kernel(const float* __restrict__ wh,
                                                     const float* __restrict__ off,
                                                     float* __restrict__ out) {
    const int b = blockIdx.x;
    const int tid = threadIdx.x;
    const int wid = tid >> 5;
    const int lane = tid & 31;

    __shared__ int s_wcnt[2][16];
    __shared__ unsigned long long s_cand[MAXCAND];
    __shared__ float s_x1[KTOP], s_y1[KTOP], s_x2[KTOP], s_y2[KTOP];
    __shared__ float s_area[KTOP], s_score[KTOP];
    __shared__ int s_cls[KTOP];
    __shared__ uint4 s_sup[KTOP];
    __shared__ unsigned int s_alive[4];
    __shared__ int s_n;

    // ---- load 32 score keys per thread into registers (coalesced) ----
    const float* cf = g_conf + (size_t)b * HWSZ;
    unsigned int key[32];
#pragma unroll
    for (int i = 0; i < 32; ++i)
        key[i] = __float_as_uint(cf[i * 512 + tid]);   // idx = i*512 + tid

    // ---- rank-100 threshold by bisection; counts via reduce+smem, no atomics.
    // Invariant: count(lo) >= KTOP > count(hi). Keys are in {0} U (0.3, 1.0).
    unsigned int lo = 1u, hi = 0x3F800000u;            // 1.0f: strict upper bound
    unsigned int probe = 0x3F7F0000u;                  // seed ~0.99609 (narrows fast)
    int par = 0;
    while (true) {
        int c = 0;
#pragma unroll
        for (int i = 0; i < 32; ++i) c += (key[i] >= probe);
        c = __reduce_add_sync(0xffffffffu, c);
        if (lane == 0) s_wcnt[par][wid] = c;
        __syncthreads();
        int cnt = 0;
#pragma unroll
        for (int w = 0; w < 16; ++w) cnt += s_wcnt[par][w];
        par ^= 1;
        if (cnt >= KTOP) lo = probe; else hi = probe;
        if (hi - lo <= 1u) break;
        probe = lo + ((hi - lo) >> 1);
    }
    const unsigned int thr = lo;   // lo=1 if fewer than KTOP nonzero: take all

    // ---- compact candidates key >= thr, packed (key<<32)|~idx ----
    if (tid == 0) s_n = 0;
    __syncthreads();
#pragma unroll
    for (int i = 0; i < 32; ++i) {
        if (key[i] >= thr) {
            int p = atomicAdd(&s_n, 1);
            if (p < MAXCAND) {
                unsigned int idx = (unsigned int)(i * 512 + tid);
                s_cand[p] = ((unsigned long long)key[i] << 32) | (unsigned int)(~idx);
            }
        }
    }
    __syncthreads();
    int n = s_n < MAXCAND ? s_n : MAXCAND;
    for (int p = n + tid; p < MAXCAND; p += 512) s_cand[p] = 0ULL;
    __syncthreads();

    // ---- warp-0 register bitonic sort of 256 u64, descending ----
    if (tid < 32) {
        unsigned long long v[8];
#pragma unroll
        for (int r = 0; r < 8; ++r) v[r] = s_cand[r * 32 + tid];
#pragma unroll
        for (int k = 2; k <= 256; k <<= 1) {
#pragma unroll
            for (int j = 128; j > 0; j >>= 1) {
                if (j >= k) continue;
                if (j >= 32) {
                    int jr = j >> 5;
#pragma unroll
                    for (int r = 0; r < 8; ++r) {
                        if ((r & jr) == 0) {
                            int pr = r | jr;
                            int idx = r * 32 + tid;
                            bool desc = ((idx & k) == 0);
                            unsigned long long a = v[r], bb = v[pr];
                            bool sw = desc ? (a < bb) : (a > bb);
                            if (sw) { v[r] = bb; v[pr] = a; }
                        }
                    }
                } else {
#pragma unroll
                    for (int r = 0; r < 8; ++r) {
                        unsigned long long pv = __shfl_xor_sync(0xffffffffu, v[r], j);
                        int idx = r * 32 + tid;
                        bool desc = ((idx & k) == 0);
                        bool low = ((tid & j) == 0);
                        bool keepMax = (desc == low);
                        unsigned long long mx = v[r] > pv ? v[r] : pv;
                        unsigned long long mn = v[r] > pv ? pv : v[r];
                        v[r] = keepMax ? mx : mn;
                    }
                }
            }
        }
#pragma unroll
        for (int r = 0; r < 8; ++r) s_cand[r * 32 + tid] = v[r];
    }
    if (tid < 4) s_alive[tid] = 0u;
    if (tid < KTOP) s_sup[tid] = make_uint4(0u, 0u, 0u, 0u);
    __syncthreads();

    // ---- gather top-100, decode boxes (mirrors reference FP op order) ----
    if (tid < KTOP) {
        unsigned long long pk = s_cand[tid];
        unsigned int kk = (unsigned int)(pk >> 32);
        float score = __uint_as_float(kk);
        bool valid = score > SCORE_THRESH;
        float x1 = 0.f, y1 = 0.f, x2 = 0.f, y2 = 0.f;
        int cl = 0;
        if (valid) {
            unsigned int idx = ~((unsigned int)(pk & 0xffffffffu));
            int xi = idx & (WW - 1);
            int yi = idx >> 7;
            const float* whb = wh  + (size_t)b * 2 * HWSZ;
            const float* ofb = off + (size_t)b * 2 * HWSZ;
            float bw = whb[idx];
            float bh = whb[HWSZ + idx];
            float o0 = ofb[idx];
            float o1 = ofb[HWSZ + idx];
            float cx = (float)xi + o0;
            float cy = (float)yi + o1;
            const float invW = 1.0f / (float)WW;   // exact power of two
            const float invH = 1.0f / (float)HH;
            x1 = (cx - bw * 0.5f) * invW;
            y1 = (cy - bh * 0.5f) * invH;
            x2 = (cx + bw * 0.5f) * invW;
            y2 = (cy + bh * 0.5f) * invH;
            cl = (int)g_cls[(size_t)b * HWSZ + idx];
            atomicOr(&s_alive[tid >> 5], 1u << (tid & 31));
        }
        s_x1[tid] = x1; s_y1[tid] = y1; s_x2[tid] = x2; s_y2[tid] = y2;
        s_area[tid] = (x2 - x1) * (y2 - y1);
        s_score[tid] = score;
        s_cls[tid] = cl;
    }
    __syncthreads();

    // ---- parallel suppression-matrix build (bitmask rows) ----
    for (int idx = tid; idx < KTOP * KTOP; idx += 512) {
        int i = idx / KTOP;
        int jj = idx - i * KTOP;
        if (jj > i && s_cls[i] == s_cls[jj]) {
            float lx = fmaxf(s_x1[i], s_x1[jj]);
            float ly = fmaxf(s_y1[i], s_y1[jj]);
            float rx = fminf(s_x2[i], s_x2[jj]);
            float ry = fminf(s_y2[i], s_y2[jj]);
            float iw = fmaxf(rx - lx, 0.f);
            float ih = fmaxf(ry - ly, 0.f);
            float inter = iw * ih;
            float iou = inter / (s_area[i] + s_area[jj] - inter + 1e-9f);
            if (iou > NMS_THRESH)
                atomicOr(&((unsigned int*)s_sup)[i * 4 + (jj >> 5)], 1u << (jj & 31));
        }
    }
    __syncthreads();

    // ---- serial greedy sweep over bitmasks (thread 0, row prefetch) ----
    if (tid == 0) {
        unsigned int a0 = s_alive[0], a1 = s_alive[1], a2 = s_alive[2], a3 = s_alive[3];
        uint4 row = s_sup[0];
        for (int i = 0; i < KTOP; ++i) {
            uint4 nxt = (i + 1 < KTOP) ? s_sup[i + 1] : make_uint4(0u, 0u, 0u, 0u);
            unsigned int aw = (i < 32) ? a0 : (i < 64) ? a1 : (i < 96) ? a2 : a3;
            if ((aw >> (i & 31)) & 1u) {
                a0 &= ~row.x; a1 &= ~row.y; a2 &= ~row.z; a3 &= ~row.w;
            }
            row = nxt;
        }
        s_alive[0] = a0; s_alive[1] = a1; s_alive[2] = a2; s_alive[3] = a3;
    }
    __syncthreads();

    // ---- write dets (scale to image via the reference's recompute path) ----
    if (tid < KTOP) {
        bool alive = (s_alive[tid >> 5] >> (tid & 31)) & 1u;
        float* o = out + ((size_t)b * KTOP + tid) * 6;
        if (alive) {
            float x1 = s_x1[tid], y1 = s_y1[tid], x2 = s_x2[tid], y2 = s_y2[tid];
            float cxm = (x1 + x2) * 0.5f;
            float cym = (y1 + y2) * 0.5f;
            float cw = x2 - x1;
            float ch = y2 - y1;
            o[0] = (cxm - cw * 0.5f) * 512.f;
            o[1] = (cym - ch * 0.5f) * 512.f;
            o[2] = (cxm + cw * 0.5f) * 512.f;
            o[3] = (cym + ch * 0.5f) * 512.f;
            o[4] = s_score[tid];
            o[5] = (float)s_cls[tid];
        } else {
            o[0] = 0.f; o[1] = 0.f; o[2] = 0.f;
            o[3] = 0.f; o[4] = 0.f; o[5] = 0.f;
        }
    }
}

extern "C" void kernel_launch(void* const* d_in, const int* in_sizes, int n_in,
                              void* d_out, int out_size) {
    const float* hm  = (const float*)d_in[0];
    const float* wh  = (const float*)d_in[1];
    const float* off = (const float*)d_in[2];
    float* out = (float*)d_out;

    dim3 gA(HH / 16, NB);     // 8 x 32 = 256 blocks
    peak_kernel<<<gA, 256>>>(hm);
    select_kernel<<<NB, 512>>>(wh, off, out);
}